// round 16
// baseline (speedup 1.0000x reference)
#include <cuda_runtime.h>
#include <cuda_bf16.h>

// preds: [128, 4096, 50] float32 -> 26,214,400 elems (d_in[0])
// gt:    [128, 4096]     int32   ->    524,288 elems (d_in[1])
// out:   scalar float32
//
// loss = [ LN2*(sum_all log2(1+exp(p)) - sum_{unvoiced} log2(1+exp(p)))
//          - sum_{voiced} p.tgt ] / (50 * n_voiced)
//
// R15 champion frame (27.1us); phase A's 25-iter reflect-recompute replaced
// by the CLOSED-FORM 5-tap dot (pure ALU, no smem -- every LDS variant
// regressed). Derived adjoint of the reflect-padded blur of one_hot(q):
//   q>=3: dot = K2*r[q] + K1*(r[q-1]+r[q+1]) + K0*(r[q-2]+r[q+2])
//   q==0: K2*r0 + K1*r1 + K0*r2
//   q==1: 2K1*r0 + (K2+K0)*r1 + K1*r2 + K0*r3
//   q==2: 2K0*r0 + K1*r1 + K2*r2 + K1*r3 + K0*r4
// (q <= 24 since gt <= 199, so upper reflect edge never triggers)

#define NF4       6553600u
#define ROWS      524288u
#define NBINS     50

#define SP_BLOCKS  1216u         // 152 * 8, single wave on GB300
#define SP_THREADS 256u
#define NTHREADS   (SP_BLOCKS * SP_THREADS)   // 311296

#define GK0 2.6386456e-4f
#define GK1 0.10645078f
#define GK2 0.78657072f

__device__ float    g_part[SP_BLOCKS];
__device__ int      g_cntp[SP_BLOCKS];
__device__ unsigned g_done;              // ticket; reset by last block

__device__ __forceinline__ float sp2(float p) {   // log2(1 + exp(p))
    return __log2f(1.0f + __expf(p));
}

// prod *= (1 + exp(p))  ==  fma(prod, exp(p), prod)
__device__ __forceinline__ void pmul(float& pr, float p) {
    pr = fmaf(pr, __expf(p), pr);
}

__global__ __launch_bounds__(SP_THREADS, 8) void pitchloss_kernel(
    const float* __restrict__ preds, const int* __restrict__ gt,
    float* __restrict__ out)
{
    const int      tid  = threadIdx.x;
    const unsigned gtid = blockIdx.x * SP_THREADS + tid;

    // ---------------- phase A: per-row work (voiced dot / unvoiced corr) --
    float dot = 0.0f, neg = 0.0f;
    int   cnt = 0;
    for (unsigned r = gtid; r < ROWS; r += NTHREADS) {
        int g = gt[r];
        const float* row = preds + (size_t)r * NBINS;
        if (g != 100) {
            cnt++;
            int q = (g > 50) ? min((g - 50) / 6, NBINS - 1) : 0;   // <= 24
            if (q >= 3) {
                float c  = __ldg(row + q);
                float l1 = __ldg(row + q - 1);
                float h1 = __ldg(row + q + 1);
                float l2 = __ldg(row + q - 2);
                float h2 = __ldg(row + q + 2);
                dot = fmaf(GK2, c, dot);
                dot = fmaf(GK1, l1 + h1, dot);
                dot = fmaf(GK0, l2 + h2, dot);
            } else {
                float r0 = __ldg(row + 0);
                float r1 = __ldg(row + 1);
                float r2 = __ldg(row + 2);
                if (q == 0) {
                    dot = fmaf(GK2, r0, dot);
                    dot = fmaf(GK1, r1, dot);
                    dot = fmaf(GK0, r2, dot);
                } else if (q == 1) {
                    float r3 = __ldg(row + 3);
                    dot = fmaf(2.0f * GK1, r0, dot);
                    dot = fmaf(GK2 + GK0, r1, dot);
                    dot = fmaf(GK1, r2, dot);
                    dot = fmaf(GK0, r3, dot);
                } else {  // q == 2
                    float r3 = __ldg(row + 3);
                    float r4 = __ldg(row + 4);
                    dot = fmaf(2.0f * GK0, r0, dot);
                    dot = fmaf(GK1, r1 + r3, dot);
                    dot = fmaf(GK2, r2, dot);
                    dot = fmaf(GK0, r4, dot);
                }
            }
        } else {
            // rare (~0.5%)
            #pragma unroll 5
            for (int n = 0; n < NBINS; n++)
                neg += sp2(__ldg(row + n));
        }
    }

    // ---------------- phase B: streaming softplus over ALL elements -------
    const float4* p4 = reinterpret_cast<const float4*>(preds);
    float acc = 0.0f;
    unsigned i = gtid;
    for (; i + 3u * NTHREADS < NF4; i += 4u * NTHREADS) {
        float4 a = p4[i];
        float4 b = p4[i +      NTHREADS];
        float4 c = p4[i + 2u * NTHREADS];
        float4 d = p4[i + 3u * NTHREADS];
        float pr1 = 1.0f + __expf(a.x);
        pmul(pr1, a.y); pmul(pr1, a.z); pmul(pr1, a.w);
        pmul(pr1, b.x); pmul(pr1, b.y); pmul(pr1, b.z); pmul(pr1, b.w);
        float pr2 = 1.0f + __expf(c.x);
        pmul(pr2, c.y); pmul(pr2, c.z); pmul(pr2, c.w);
        pmul(pr2, d.x); pmul(pr2, d.y); pmul(pr2, d.z); pmul(pr2, d.w);
        acc += __log2f(pr1) + __log2f(pr2);
    }
    for (; i < NF4; i += NTHREADS) {
        float4 a = p4[i];
        float pr = 1.0f + __expf(a.x);
        pmul(pr, a.y); pmul(pr, a.z); pmul(pr, a.w);
        acc += __log2f(pr);
    }

    // ---------------- block reduction -------------------------------------
    const float LN2 = 0.69314718055994530942f;
    float part = fmaf(LN2, acc - neg, -dot);

    __shared__ float sp[SP_THREADS];
    __shared__ int   sc[SP_THREADS];
    sp[tid] = part; sc[tid] = cnt;
    __syncthreads();
    #pragma unroll
    for (int o = SP_THREADS / 2; o > 0; o >>= 1) {
        if (tid < o) { sp[tid] += sp[tid + o]; sc[tid] += sc[tid + o]; }
        __syncthreads();
    }

    __shared__ bool s_last;
    if (tid == 0) {
        g_part[blockIdx.x] = sp[0];
        g_cntp[blockIdx.x] = sc[0];
        __threadfence();
        unsigned t = atomicAdd(&g_done, 1u);
        s_last = (t == SP_BLOCKS - 1);
    }
    __syncthreads();

    // ---------------- last block: deterministic ordered finalize ----------
    if (s_last) {
        float a = 0.0f; int c = 0;
        for (unsigned j = tid; j < SP_BLOCKS; j += SP_THREADS) {
            a += g_part[j]; c += g_cntp[j];
        }
        sp[tid] = a; sc[tid] = c;
        __syncthreads();
        #pragma unroll
        for (int o = SP_THREADS / 2; o > 0; o >>= 1) {
            if (tid < o) { sp[tid] += sp[tid + o]; sc[tid] += sc[tid + o]; }
            __syncthreads();
        }
        if (tid == 0) {
            out[0] = sp[0] / (50.0f * (float)sc[0]);
            g_done = 0;   // reset for next (graph-replayed) launch
        }
    }
}

extern "C" void kernel_launch(void* const* d_in, const int* in_sizes, int n_in,
                              void* d_out, int out_size)
{
    const float* preds = (const float*)d_in[0];
    const int*   gt    = (const int*)d_in[1];
    float* out = (float*)d_out;

    pitchloss_kernel<<<SP_BLOCKS, SP_THREADS>>>(preds, gt, out);
}

// round 17
// speedup vs baseline: 1.0083x; 1.0083x over previous
#include <cuda_runtime.h>
#include <cuda_bf16.h>

// preds: [128, 4096, 50] float32 -> 26,214,400 elems (d_in[0])
// gt:    [128, 4096]     int32   ->    524,288 elems (d_in[1])
// out:   scalar float32
//
// loss = [ LN2*(sum_all log2(1+exp(p)) - sum_{unvoiced} log2(1+exp(p)))
//          - sum_{voiced} p.tgt ] / (50 * n_voiced)
//
// R16 frame; voiced-row gather now 3x LDG.64 (8B-aligned windows -- legal for
// EVERY row; R12's float4 crashed on odd rows) instead of 5 scalar LDGs:
// L1tex wavefronts/row drop 5 -> 3 (phase A is wavefront-bound, ~9us/SM).
// Taps selected by off=(q-2)&1 (pure ALU SELs); q<=2 uses the closed-form
// reflect-edge formulas (validated in R16) on the same 3 loads. No smem.

#define NF4       6553600u
#define ROWS      524288u
#define NBINS     50

#define SP_BLOCKS  1216u         // 152 * 8, single wave on GB300
#define SP_THREADS 256u
#define NTHREADS   (SP_BLOCKS * SP_THREADS)   // 311296

#define GK0 2.6386456e-4f
#define GK1 0.10645078f
#define GK2 0.78657072f

__device__ float    g_part[SP_BLOCKS];
__device__ int      g_cntp[SP_BLOCKS];
__device__ unsigned g_done;              // ticket; reset by last block

__device__ __forceinline__ float sp2(float p) {   // log2(1 + exp(p))
    return __log2f(1.0f + __expf(p));
}

// prod *= (1 + exp(p))  ==  fma(prod, exp(p), prod)
__device__ __forceinline__ void pmul(float& pr, float p) {
    pr = fmaf(pr, __expf(p), pr);
}

__global__ __launch_bounds__(SP_THREADS, 8) void pitchloss_kernel(
    const float* __restrict__ preds, const int* __restrict__ gt,
    float* __restrict__ out)
{
    const int      tid  = threadIdx.x;
    const unsigned gtid = blockIdx.x * SP_THREADS + tid;

    // ---------------- phase A: per-row work (voiced dot / unvoiced corr) --
    float dot = 0.0f, neg = 0.0f;
    int   cnt = 0;
    for (unsigned r = gtid; r < ROWS; r += NTHREADS) {
        int g = gt[r];
        const float* row = preds + (size_t)r * NBINS;
        if (g != 100) {
            cnt++;
            int q = (g > 50) ? min((g - 50) / 6, NBINS - 1) : 0;   // <= 24
            int c2  = (q >= 3) ? ((q - 2) >> 1) : 0;
            const float2* w = reinterpret_cast<const float2*>(row) + c2;
            float2 w0 = __ldg(w);
            float2 w1 = __ldg(w + 1);
            float2 w2 = __ldg(w + 2);
            if (q >= 3) {
                // window [2c2, 2c2+5] covers [q-2, q+2]; off selects phase
                bool off = ((q - 2) & 1) != 0;
                float s0 = off ? w0.y : w0.x;
                float s1 = off ? w1.x : w0.y;
                float s2 = off ? w1.y : w1.x;
                float s3 = off ? w2.x : w1.y;
                float s4 = off ? w2.y : w2.x;
                dot = fmaf(GK2, s2, dot);
                dot = fmaf(GK1, s1 + s3, dot);
                dot = fmaf(GK0, s0 + s4, dot);
            } else {
                // reflect-edge closed forms (c2 == 0: w = r0..r5)
                if (q == 0) {
                    dot = fmaf(GK2, w0.x, dot);
                    dot = fmaf(GK1, w0.y, dot);
                    dot = fmaf(GK0, w1.x, dot);
                } else if (q == 1) {
                    dot = fmaf(2.0f * GK1, w0.x, dot);
                    dot = fmaf(GK2 + GK0, w0.y, dot);
                    dot = fmaf(GK1, w1.x, dot);
                    dot = fmaf(GK0, w1.y, dot);
                } else {  // q == 2
                    dot = fmaf(2.0f * GK0, w0.x, dot);
                    dot = fmaf(GK1, w0.y + w1.y, dot);
                    dot = fmaf(GK2, w1.x, dot);
                    dot = fmaf(GK0, w2.x, dot);
                }
            }
        } else {
            // rare (~0.5%)
            #pragma unroll 5
            for (int n = 0; n < NBINS; n++)
                neg += sp2(__ldg(row + n));
        }
    }

    // ---------------- phase B: streaming softplus over ALL elements -------
    const float4* p4 = reinterpret_cast<const float4*>(preds);
    float acc = 0.0f;
    unsigned i = gtid;
    for (; i + 3u * NTHREADS < NF4; i += 4u * NTHREADS) {
        float4 a = p4[i];
        float4 b = p4[i +      NTHREADS];
        float4 c = p4[i + 2u * NTHREADS];
        float4 d = p4[i + 3u * NTHREADS];
        float pr1 = 1.0f + __expf(a.x);
        pmul(pr1, a.y); pmul(pr1, a.z); pmul(pr1, a.w);
        pmul(pr1, b.x); pmul(pr1, b.y); pmul(pr1, b.z); pmul(pr1, b.w);
        float pr2 = 1.0f + __expf(c.x);
        pmul(pr2, c.y); pmul(pr2, c.z); pmul(pr2, c.w);
        pmul(pr2, d.x); pmul(pr2, d.y); pmul(pr2, d.z); pmul(pr2, d.w);
        acc += __log2f(pr1) + __log2f(pr2);
    }
    for (; i < NF4; i += NTHREADS) {
        float4 a = p4[i];
        float pr = 1.0f + __expf(a.x);
        pmul(pr, a.y); pmul(pr, a.z); pmul(pr, a.w);
        acc += __log2f(pr);
    }

    // ---------------- block reduction -------------------------------------
    const float LN2 = 0.69314718055994530942f;
    float part = fmaf(LN2, acc - neg, -dot);

    __shared__ float sp[SP_THREADS];
    __shared__ int   sc[SP_THREADS];
    sp[tid] = part; sc[tid] = cnt;
    __syncthreads();
    #pragma unroll
    for (int o = SP_THREADS / 2; o > 0; o >>= 1) {
        if (tid < o) { sp[tid] += sp[tid + o]; sc[tid] += sc[tid + o]; }
        __syncthreads();
    }

    __shared__ bool s_last;
    if (tid == 0) {
        g_part[blockIdx.x] = sp[0];
        g_cntp[blockIdx.x] = sc[0];
        __threadfence();
        unsigned t = atomicAdd(&g_done, 1u);
        s_last = (t == SP_BLOCKS - 1);
    }
    __syncthreads();

    // ---------------- last block: deterministic ordered finalize ----------
    if (s_last) {
        float a = 0.0f; int c = 0;
        for (unsigned j = tid; j < SP_BLOCKS; j += SP_THREADS) {
            a += g_part[j]; c += g_cntp[j];
        }
        sp[tid] = a; sc[tid] = c;
        __syncthreads();
        #pragma unroll
        for (int o = SP_THREADS / 2; o > 0; o >>= 1) {
            if (tid < o) { sp[tid] += sp[tid + o]; sc[tid] += sc[tid + o]; }
            __syncthreads();
        }
        if (tid == 0) {
            out[0] = sp[0] / (50.0f * (float)sc[0]);
            g_done = 0;   // reset for next (graph-replayed) launch
        }
    }
}

extern "C" void kernel_launch(void* const* d_in, const int* in_sizes, int n_in,
                              void* d_out, int out_size)
{
    const float* preds = (const float*)d_in[0];
    const int*   gt    = (const int*)d_in[1];
    float* out = (float*)d_out;

    pitchloss_kernel<<<SP_BLOCKS, SP_THREADS>>>(preds, gt, out);
}